// round 6
// baseline (speedup 1.0000x reference)
#include <cuda_runtime.h>
#include <cuda_fp16.h>
#include <cstdint>

#define NUM_USERS 50000
#define NUM_ITEMS 50000
#define NUM_NODES (NUM_USERS + NUM_ITEMS)   // 100000
#define EMB_DIM 128
#define NUM_EDGES 2000000
#define TOTAL_ELEMS (NUM_NODES * EMB_DIM)   // 12,800,000 floats
#define TOTAL_VEC4 (TOTAL_ELEMS / 4)        // 3,200,000 uint2-half4 per buffer

#define ELL_CAP 96   // max row degree headroom (Poisson mean 20, max ~47)

// ---- device scratch (no allocation allowed) ----
// INVARIANTS (maintained every call):
//  * g_cnt all-zero at entry (zero-init at load; FINAL spmm re-zeroes).
//  * g_ell slots >= cnt[r] for each row are NEVER written -> stay zero from
//    module-load zero-init -> {col=0, val=0.0f}. SpMM exploits this to read
//    rows rounded up to a multiple of 4 with no tail handling.
__device__ int   g_cnt[NUM_NODES];
__device__ int2  g_ell[(size_t)NUM_NODES * ELL_CAP];   // {col, val-as-int(f32)}
// fp16 feature buffers: 128 halves per node = 32 uint2 per node
__device__ uint2 g_h0[TOTAL_VEC4];
__device__ uint2 g_h1[TOTAL_VEC4];
__device__ uint2 g_h2[TOTAL_VEC4];

// ---------------------------------------------------------------------------
// fused prologue:
//   i < TOTAL_VEC4      : convert emb (f32) -> h0 (fp16)
//   i < NUM_EDGES/4     : ELL scatter, 4 edges/thread (4 independent
//                         atomicAdd chains in flight, vectorized edge loads)
// ---------------------------------------------------------------------------
__global__ void k_prologue(const float* __restrict__ emb,
                           const int* __restrict__ rows,
                           const int* __restrict__ cols,
                           const float* __restrict__ vals) {
    int i = blockIdx.x * blockDim.x + threadIdx.x;

    if (i < NUM_EDGES / 4) {
        int base = i * 4;
        int4   r4 = *(const int4*)  (rows + base);
        int4   c4 = *(const int4*)  (cols + base);
        float4 v4 = *(const float4*)(vals + base);

        int p0 = atomicAdd(&g_cnt[r4.x], 1);
        int p1 = atomicAdd(&g_cnt[r4.y], 1);
        int p2 = atomicAdd(&g_cnt[r4.z], 1);
        int p3 = atomicAdd(&g_cnt[r4.w], 1);

        g_ell[(size_t)r4.x * ELL_CAP + p0] = make_int2(c4.x, __float_as_int(v4.x));
        g_ell[(size_t)r4.y * ELL_CAP + p1] = make_int2(c4.y, __float_as_int(v4.y));
        g_ell[(size_t)r4.z * ELL_CAP + p2] = make_int2(c4.z, __float_as_int(v4.z));
        g_ell[(size_t)r4.w * ELL_CAP + p3] = make_int2(c4.w, __float_as_int(v4.w));
    }

    if (i < TOTAL_VEC4) {
        float4 v = ((const float4*)emb)[i];
        __half2 lo = __floats2half2_rn(v.x, v.y);
        __half2 hi = __floats2half2_rn(v.z, v.w);
        uint2 packed;
        packed.x = *(unsigned int*)&lo;
        packed.y = *(unsigned int*)&hi;
        g_h0[i] = packed;
    }
}

// ---------------------------------------------------------------------------
// ELL SpMM on fp16 features: warp per row, 4 halves (uint2) per lane,
// f32 register accumulation, single row store.
// Tail-free: n rounded up to x4; padding slots are guaranteed {0, 0.0f}.
// Meta loaded as int4 (2 edges per LDG.128 broadcast).
// FINAL=true: fuse out = 0.25 * (emb + h1 + h2 + acc) -> f32 d_out,
//             and restore the g_cnt zero invariant.
// ---------------------------------------------------------------------------
__device__ __forceinline__ void acc_edge(float4& acc, float v, uint2 raw) {
    float2 flo = __half22float2(*(__half2*)&raw.x);
    float2 fhi = __half22float2(*(__half2*)&raw.y);
    acc.x += v * flo.x;
    acc.y += v * flo.y;
    acc.z += v * fhi.x;
    acc.w += v * fhi.y;
}

template <bool FINAL>
__global__ void k_spmm(const uint2* __restrict__ x, uint2* __restrict__ y,
                       const float* __restrict__ emb, float* __restrict__ out) {
    int w    = (blockIdx.x * blockDim.x + threadIdx.x) >> 5;
    int lane = threadIdx.x & 31;
    if (w >= NUM_NODES) return;

    int n  = __ldg(&g_cnt[w]);
    int pn = (n + 3) & ~3;                      // padded length (slots are zeros)
    const int4* meta = (const int4*)(g_ell + (size_t)w * ELL_CAP);

    float4 acc = make_float4(0.f, 0.f, 0.f, 0.f);

    for (int i = 0; i < pn; i += 4) {
        int4 ma = __ldg(meta + (i >> 1));       // edges i, i+1
        int4 mb = __ldg(meta + (i >> 1) + 1);   // edges i+2, i+3
        uint2 r0 = __ldg(x + (size_t)ma.x * 32 + lane);
        uint2 r1 = __ldg(x + (size_t)ma.z * 32 + lane);
        uint2 r2 = __ldg(x + (size_t)mb.x * 32 + lane);
        uint2 r3 = __ldg(x + (size_t)mb.z * 32 + lane);
        acc_edge(acc, __int_as_float(ma.y), r0);
        acc_edge(acc, __int_as_float(ma.w), r1);
        acc_edge(acc, __int_as_float(mb.y), r2);
        acc_edge(acc, __int_as_float(mb.w), r3);
    }

    size_t idx = (size_t)w * 32 + lane;
    if (!FINAL) {
        __half2 lo = __floats2half2_rn(acc.x, acc.y);
        __half2 hi = __floats2half2_rn(acc.z, acc.w);
        uint2 packed;
        packed.x = *(unsigned int*)&lo;
        packed.y = *(unsigned int*)&hi;
        y[idx] = packed;
    } else {
        if (lane == 0) g_cnt[w] = 0;   // restore zero invariant for next call
        float4 m = ((const float4*)emb)[idx];
        uint2 a = __ldg(&g_h1[idx]);
        uint2 b = __ldg(&g_h2[idx]);
        float2 a_lo = __half22float2(*(__half2*)&a.x);
        float2 a_hi = __half22float2(*(__half2*)&a.y);
        float2 b_lo = __half22float2(*(__half2*)&b.x);
        float2 b_hi = __half22float2(*(__half2*)&b.y);
        float4 o;
        o.x = 0.25f * (m.x + a_lo.x + b_lo.x + acc.x);
        o.y = 0.25f * (m.y + a_lo.y + b_lo.y + acc.y);
        o.z = 0.25f * (m.z + a_hi.x + b_hi.x + acc.z);
        o.w = 0.25f * (m.w + a_hi.y + b_hi.y + acc.w);
        ((float4*)out)[idx] = o;
    }
}

extern "C" void kernel_launch(void* const* d_in, const int* in_sizes, int n_in,
                              void* d_out, int out_size) {
    const float* emb  = (const float*)d_in[0];
    const int*   rows = (const int*)  d_in[1];
    const int*   cols = (const int*)  d_in[2];
    const float* vals = (const float*)d_in[3];
    float*       out  = (float*)d_out;

    uint2 *h0 = nullptr, *h1 = nullptr, *h2 = nullptr;
    cudaGetSymbolAddress((void**)&h0, g_h0);
    cudaGetSymbolAddress((void**)&h1, g_h1);
    cudaGetSymbolAddress((void**)&h2, g_h2);

    const int TB = 256;
    const int pro_blocks  = (TOTAL_VEC4 + TB - 1) / TB;          // covers both ranges
    const int spmm_blocks = (NUM_NODES * 32 + TB - 1) / TB;

    // fused convert + ELL scatter
    k_prologue<<<pro_blocks, TB>>>(emb, rows, cols, vals);

    // 3 propagation layers; layer 3 fuses the final average into d_out
    k_spmm<false><<<spmm_blocks, TB>>>(h0, h1, nullptr, nullptr);
    k_spmm<false><<<spmm_blocks, TB>>>(h1, h2, nullptr, nullptr);
    k_spmm<true ><<<spmm_blocks, TB>>>(h2, nullptr, emb, out);
}